// round 15
// baseline (speedup 1.0000x reference)
#include <cuda_runtime.h>
#include <cuda_fp16.h>
#include <math.h>
#include <stdint.h>

#define N 8192
#define DIM 256
#define NT 64
#define NTILES (NT * (NT + 1) / 2)
#define MARGIN 0.3f

// ---- device scratch ----
__device__ __half   g_Xhi[N * DIM];
__device__ float    g_SQ[N];
__device__ int      g_TGT[N];
__device__ unsigned g_AP[N];
__device__ unsigned g_AN[N];

// ---- smem layout (relative to 1024-aligned base) ----
// two stages of 2 tiles (Ahi, Bhi), each tile 128 rows x 64 k fp16 = 16KB
#define T_AHI 0
#define T_BHI 16384
#define S_STAGE(s) ((s) * 32768)
#define S_LABR 65536
#define S_LABC (S_LABR + 512)
#define S_SQR  (S_LABC + 512)
#define S_SQC  (S_SQR + 512)
#define S_RRAP (S_SQC + 512)      // 128*4 floats
#define S_RRAN (S_RRAP + 2048)
#define S_CCAP (S_RRAN + 2048)    // 128*2 floats
#define S_CCAN (S_CCAP + 1024)
#define SMEM_SZ (S_CCAN + 1024 + 1024)

// ---- PTX helpers (base sm_103-safe) ----
__device__ __forceinline__ uint32_t smem_u32(const void* p) {
    uint32_t a;
    asm("{ .reg .u64 t; cvta.to.shared.u64 t, %1; cvt.u32.u64 %0, t; }"
        : "=r"(a) : "l"(p));
    return a;
}
#define CP16(dst, src) \
    asm volatile("cp.async.cg.shared.global [%0], [%1], 16;" :: "r"(dst), "l"(src))
#define CP_COMMIT() asm volatile("cp.async.commit_group;")
#define CP_WAIT(n)  asm volatile("cp.async.wait_group %0;" :: "n"(n))
#define LDSM4(r, a)                                                           \
    asm volatile("ldmatrix.sync.aligned.m8n8.x4.shared.b16 {%0,%1,%2,%3}, [%4];" \
        : "=r"((r)[0]), "=r"((r)[1]), "=r"((r)[2]), "=r"((r)[3]) : "r"(a))
#define MMA16816(d, a, b)                                                     \
    asm volatile("mma.sync.aligned.m16n8k16.row.col.f32.f16.f16.f32 "        \
        "{%0,%1,%2,%3}, {%4,%5,%6,%7}, {%8,%9}, {%0,%1,%2,%3};"              \
        : "+f"((d)[0]), "+f"((d)[1]), "+f"((d)[2]), "+f"((d)[3])             \
        : "r"((a)[0]), "r"((a)[1]), "r"((a)[2]), "r"((a)[3]),                \
          "r"((b)[0]), "r"((b)[1]))

__device__ __forceinline__ float bmax(float v, int m) {
    return fmaxf(v, __shfl_xor_sync(0xffffffffu, v, m));
}
__device__ __forceinline__ float bmin(float v, int m) {
    return fminf(v, __shfl_xor_sync(0xffffffffu, v, m));
}

// ------------------------------------------------------------------
// normalize: warp per 2 rows (MLP=4); per-block dtype detection;
// resets per-row AP/AN. grid = N/16 = 512 blocks.
// ------------------------------------------------------------------
__global__ __launch_bounds__(256) void norm_kernel(const float* __restrict__ in,
                                                   const int* __restrict__ t32) {
    int warp = threadIdx.x >> 5;
    int lane = threadIdx.x & 31;
    int row0 = blockIdx.x * 16 + warp * 2;
    int row1 = row0 + 1;

    int odd = 0;
    if (lane == 0)
        odd = t32[2 * (row0 & 4095) + 1] | t32[2 * (row1 & 4095) + 1];
    int any = __syncthreads_or(odd);
    bool is64 = (any == 0);

    // front-batched loads: 4 independent float4 per lane
    const float4* p0 = (const float4*)(in + (size_t)row0 * DIM);
    const float4* p1 = (const float4*)(in + (size_t)row1 * DIM);
    float4 a0 = p0[lane * 2];
    float4 b0 = p0[lane * 2 + 1];
    float4 a1 = p1[lane * 2];
    float4 b1 = p1[lane * 2 + 1];
    float v0[8] = { a0.x, a0.y, a0.z, a0.w, b0.x, b0.y, b0.z, b0.w };
    float v1[8] = { a1.x, a1.y, a1.z, a1.w, b1.x, b1.y, b1.z, b1.w };

    float s0 = 0.0f, s1 = 0.0f;
    #pragma unroll
    for (int k = 0; k < 8; k++) {
        s0 = fmaf(v0[k], v0[k], s0);
        s1 = fmaf(v1[k], v1[k], s1);
    }
    #pragma unroll
    for (int m = 16; m > 0; m >>= 1) {
        s0 += __shfl_xor_sync(0xffffffffu, s0, m);
        s1 += __shfl_xor_sync(0xffffffffu, s1, m);
    }

    float inv0 = 1.0f / (sqrtf(s0) + 1e-12f);
    float inv1 = 1.0f / (sqrtf(s1) + 1e-12f);
    float x0[8], x1[8];
    float q0 = 0.0f, q1 = 0.0f;
    #pragma unroll
    for (int k = 0; k < 8; k++) {
        x0[k] = v0[k] * inv0; q0 = fmaf(x0[k], x0[k], q0);
        x1[k] = v1[k] * inv1; q1 = fmaf(x1[k], x1[k], q1);
    }
    #pragma unroll
    for (int m = 16; m > 0; m >>= 1) {
        q0 += __shfl_xor_sync(0xffffffffu, q0, m);
        q1 += __shfl_xor_sync(0xffffffffu, q1, m);
    }

    __half h0[8], h1[8];
    #pragma unroll
    for (int k = 0; k < 8; k++) {
        h0[k] = __float2half_rn(x0[k]);
        h1[k] = __float2half_rn(x1[k]);
    }
    *(uint4*)(g_Xhi + (size_t)row0 * DIM + lane * 8) = *(const uint4*)h0;
    *(uint4*)(g_Xhi + (size_t)row1 * DIM + lane * 8) = *(const uint4*)h1;

    if (lane == 0) {
        g_SQ[row0] = q0;
        g_SQ[row1] = q1;
        g_TGT[row0] = is64 ? t32[2 * row0] : t32[row0];
        g_TGT[row1] = is64 ? t32[2 * row1] : t32[row1];
        g_AP[row0] = 0u;  g_AP[row1] = 0u;
        g_AN[row0] = 0x7f800000u;  g_AN[row1] = 0x7f800000u;
    }
}

// ------------------------------------------------------------------
__device__ __forceinline__ void load_stage(
    uint32_t sb, int stg, int k0, int tid,
    const __half* a0, const __half* b0)
{
    uint32_t base = sb + S_STAGE(stg);
    const __half* src[2] = { a0 + k0, b0 + k0 };
    #pragma unroll
    for (int p = 0; p < 2; p++) {
        uint32_t tb = base + p * 16384;
        #pragma unroll
        for (int i = 0; i < 4; i++) {
            int v = tid + i * 256;
            int r = v >> 3, c8 = v & 7;
            uint32_t d = tb + r * 128 + ((c8 ^ (r & 7)) << 4);
            CP16(d, src[p] + (size_t)r * DIM + c8 * 8);
        }
    }
    CP_COMMIT();
}

// 256 threads: 8 warps in a 2x4 grid, each warp owns a 64x32 subtile
// (identical mainloop to the measured-best config)
__global__ __launch_bounds__(256, 2) void pair_kernel() {
    extern __shared__ char dsm[];
    uint32_t raw = smem_u32(dsm);
    uint32_t sb = (raw + 1023u) & ~1023u;
    char* ab = dsm + (sb - raw);

    // triangular tile index -> (it, jt), it <= jt
    int t = blockIdx.x;
    int it = (int)((129.0 - sqrt(16641.0 - 8.0 * (double)t)) * 0.5);
    while ((it + 1) * (129 - (it + 1)) / 2 <= t) it++;
    while (it * (129 - it) / 2 > t) it--;
    int jt = it + (t - it * (129 - it) / 2);

    const int rowBase = it * 128;
    const int colBase = jt * 128;
    const bool diag = (it == jt);

    const int tid = threadIdx.x;
    const int wid = tid >> 5;
    const int lane = tid & 31;
    const int wm = wid & 1;
    const int wn = wid >> 1;

    if (tid < 128) {
        ((int*)(ab + S_LABR))[tid]  = g_TGT[rowBase + tid];
        ((float*)(ab + S_SQR))[tid] = g_SQ[rowBase + tid];
    } else {
        int u = tid - 128;
        ((int*)(ab + S_LABC))[u]  = g_TGT[colBase + u];
        ((float*)(ab + S_SQC))[u] = g_SQ[colBase + u];
    }

    const __half* a0 = g_Xhi + (size_t)rowBase * DIM;
    const __half* b0 = g_Xhi + (size_t)colBase * DIM;

    float acc[4][4][4];
    #pragma unroll
    for (int mf = 0; mf < 4; mf++)
        #pragma unroll
        for (int nf = 0; nf < 4; nf++)
            #pragma unroll
            for (int e = 0; e < 4; e++) acc[mf][nf][e] = 0.0f;

    int arow[4], brow[4];
    #pragma unroll
    for (int mf = 0; mf < 4; mf++) arow[mf] = wm * 64 + mf * 16 + (lane & 15);
    #pragma unroll
    for (int nf = 0; nf < 4; nf++) brow[nf] = wn * 32 + nf * 8 + (lane & 7);
    const int ahalf = lane >> 4;
    const int bq = lane >> 3;

    load_stage(sb, 0, 0, tid, a0, b0);

    #pragma unroll 1
    for (int c = 0; c < 4; c++) {
        if (c < 3) {
            load_stage(sb, (c + 1) & 1, (c + 1) * 64, tid, a0, b0);
            CP_WAIT(1);
        } else {
            CP_WAIT(0);
        }
        __syncthreads();

        uint32_t base = sb + S_STAGE(c & 1);
        #pragma unroll
        for (int s2 = 0; s2 < 2; s2++) {
            uint32_t bh[4][4];
            #pragma unroll
            for (int nf = 0; nf < 4; nf++) {
                uint32_t swo = (((s2 * 4 + bq) ^ (brow[nf] & 7)) << 4);
                LDSM4(bh[nf], base + T_BHI + brow[nf] * 128 + swo);
            }
            #pragma unroll
            for (int ks = 0; ks < 2; ks++) {
                int s = s2 * 2 + ks;
                uint32_t ah[4][4];
                #pragma unroll
                for (int mf = 0; mf < 4; mf++) {
                    uint32_t swo = (((s * 2 + ahalf) ^ (arow[mf] & 7)) << 4);
                    LDSM4(ah[mf], base + T_AHI + arow[mf] * 128 + swo);
                }
                #pragma unroll
                for (int mf = 0; mf < 4; mf++)
                    #pragma unroll
                    for (int nf = 0; nf < 4; nf++)
                        MMA16816(acc[mf][nf], ah[mf], &bh[nf][2 * ks]);
            }
        }
        __syncthreads();
    }

    // ---- epilogue: dual-direction masked reduction ----
    int rlab[4][2], clab[4][2];
    float rsqv[4][2], csqv[4][2];
    #pragma unroll
    for (int mf = 0; mf < 4; mf++)
        #pragma unroll
        for (int sl = 0; sl < 2; sl++) {
            int r = wm * 64 + mf * 16 + sl * 8 + (lane >> 2);
            rlab[mf][sl] = ((const int*)(ab + S_LABR))[r];
            rsqv[mf][sl] = ((const float*)(ab + S_SQR))[r];
        }
    #pragma unroll
    for (int nf = 0; nf < 4; nf++)
        #pragma unroll
        for (int cp = 0; cp < 2; cp++) {
            int cc = wn * 32 + nf * 8 + (lane & 3) * 2 + cp;
            clab[nf][cp] = ((const int*)(ab + S_LABC))[cc];
            csqv[nf][cp] = ((const float*)(ab + S_SQC))[cc];
        }

    float apR[4][2], anR[4][2], apC[4][2], anC[4][2];
    #pragma unroll
    for (int q = 0; q < 4; q++)
        #pragma unroll
        for (int h = 0; h < 2; h++) {
            apR[q][h] = 0.0f; anR[q][h] = INFINITY;
            apC[q][h] = 0.0f; anC[q][h] = INFINITY;
        }

    #pragma unroll
    for (int mf = 0; mf < 4; mf++)
        #pragma unroll
        for (int nf = 0; nf < 4; nf++)
            #pragma unroll
            for (int e = 0; e < 4; e++) {
                int sl = e >> 1, cp = e & 1;
                int rl = wm * 64 + mf * 16 + sl * 8 + (lane >> 2);
                int cl = wn * 32 + nf * 8 + (lane & 3) * 2 + cp;
                float arg = fmaxf(
                    fmaf(-2.0f, acc[mf][nf][e], rsqv[mf][sl] + csqv[nf][cp]),
                    1e-12f);
                bool skip = diag && (rl == cl);
                if (!skip) {
                    if (rlab[mf][sl] == clab[nf][cp]) {
                        apR[mf][sl] = fmaxf(apR[mf][sl], arg);
                        apC[nf][cp] = fmaxf(apC[nf][cp], arg);
                    } else {
                        anR[mf][sl] = fminf(anR[mf][sl], arg);
                        anC[nf][cp] = fminf(anC[nf][cp], arg);
                    }
                }
            }

    float* rrap = (float*)(ab + S_RRAP);
    float* rran = (float*)(ab + S_RRAN);
    float* ccap = (float*)(ab + S_CCAP);
    float* ccan = (float*)(ab + S_CCAN);

    #pragma unroll
    for (int mf = 0; mf < 4; mf++)
        #pragma unroll
        for (int sl = 0; sl < 2; sl++) {
            float ap = bmax(bmax(apR[mf][sl], 1), 2);
            float an = bmin(bmin(anR[mf][sl], 1), 2);
            int r = wm * 64 + mf * 16 + sl * 8 + (lane >> 2);
            if ((lane & 3) == 0) {
                rrap[r * 4 + wn] = ap;
                rran[r * 4 + wn] = an;
            }
        }
    #pragma unroll
    for (int nf = 0; nf < 4; nf++)
        #pragma unroll
        for (int cp = 0; cp < 2; cp++) {
            float ap = bmax(bmax(bmax(apC[nf][cp], 4), 8), 16);
            float an = bmin(bmin(bmin(anC[nf][cp], 4), 8), 16);
            int cc = wn * 32 + nf * 8 + (lane & 3) * 2 + cp;
            if ((lane >> 2) == 0) {
                ccap[cc * 2 + wm] = ap;
                ccan[cc * 2 + wm] = an;
            }
        }
    __syncthreads();

    if (tid < 128) {
        float ap = fmaxf(fmaxf(rrap[tid * 4 + 0], rrap[tid * 4 + 1]),
                         fmaxf(rrap[tid * 4 + 2], rrap[tid * 4 + 3]));
        float an = fminf(fminf(rran[tid * 4 + 0], rran[tid * 4 + 1]),
                         fminf(rran[tid * 4 + 2], rran[tid * 4 + 3]));
        atomicMax((int*)&g_AP[rowBase + tid], __float_as_int(ap));
        atomicMin((int*)&g_AN[rowBase + tid], __float_as_int(an));

        float apc = fmaxf(ccap[tid * 2 + 0], ccap[tid * 2 + 1]);
        float anc = fminf(ccan[tid * 2 + 0], ccan[tid * 2 + 1]);
        atomicMax((int*)&g_AP[colBase + tid], __float_as_int(apc));
        atomicMin((int*)&g_AN[colBase + tid], __float_as_int(anc));
    }
}

// ------------------------------------------------------------------
// finalize: ONE 1024-thread block, no atomics, deterministic tree
// ------------------------------------------------------------------
__global__ __launch_bounds__(1024) void final_kernel(float* __restrict__ out) {
    __shared__ float sh[1024];
    int tid = threadIdx.x;
    float sum = 0.0f;
    #pragma unroll
    for (int k = 0; k < 8; k++) {
        int i = tid + k * 1024;
        unsigned apb = g_AP[i];
        unsigned anb = g_AN[i];
        float dap = (apb == 0u) ? 0.0f : sqrtf(__uint_as_float(apb));
        float dan = (anb == 0x7f800000u) ? (MARGIN + 1.0f)
                                         : sqrtf(__uint_as_float(anb));
        sum += fmaxf(0.0f, dap - dan + MARGIN);
    }
    sh[tid] = sum;
    __syncthreads();
    #pragma unroll
    for (int s = 512; s > 0; s >>= 1) {
        if (tid < s) sh[tid] += sh[tid + s];
        __syncthreads();
    }
    if (tid == 0) out[0] = sh[0] / (float)N;
}

// ------------------------------------------------------------------
extern "C" void kernel_launch(void* const* d_in, const int* in_sizes, int n_in,
                              void* d_out, int out_size) {
    const float* inputs = (const float*)d_in[0];
    const int* targets32 = (const int*)d_in[1];
    float* out = (float*)d_out;

    cudaFuncSetAttribute(pair_kernel,
                         cudaFuncAttributeMaxDynamicSharedMemorySize, SMEM_SZ);

    norm_kernel<<<N / 16, 256>>>(inputs, targets32);
    pair_kernel<<<NTILES, 256, SMEM_SZ>>>();
    final_kernel<<<1, 1024>>>(out);
}

// round 16
// speedup vs baseline: 1.0351x; 1.0351x over previous
#include <cuda_runtime.h>
#include <cuda_fp16.h>
#include <math.h>
#include <stdint.h>

#define N 8192
#define DIM 256
#define NT 64
#define NTILES (NT * (NT + 1) / 2)
#define MARGIN 0.3f

// ---- device scratch ----
__device__ __half   g_Xhi[N * DIM];
__device__ float    g_SQ[N];
__device__ int      g_TGT[N];
__device__ unsigned g_AP[N];
__device__ unsigned g_AN[N];
__device__ unsigned long long g_SUM;
__device__ unsigned g_DONE;

// ---- smem layout (relative to 1024-aligned base) ----
// two stages of 2 tiles (Ahi, Bhi), each tile 128 rows x 64 k fp16 = 16KB
#define T_AHI 0
#define T_BHI 16384
#define S_STAGE(s) ((s) * 32768)
#define S_LABR 65536
#define S_LABC (S_LABR + 512)
#define S_SQR  (S_LABC + 512)
#define S_SQC  (S_SQR + 512)
#define S_RRAP (S_SQC + 512)      // 128*4 floats
#define S_RRAN (S_RRAP + 2048)
#define S_CCAP (S_RRAN + 2048)    // 128*2 floats
#define S_CCAN (S_CCAP + 1024)
#define SMEM_SZ (S_CCAN + 1024 + 1024)

// ---- PTX helpers (base sm_103-safe) ----
__device__ __forceinline__ uint32_t smem_u32(const void* p) {
    uint32_t a;
    asm("{ .reg .u64 t; cvta.to.shared.u64 t, %1; cvt.u32.u64 %0, t; }"
        : "=r"(a) : "l"(p));
    return a;
}
#define CP16(dst, src) \
    asm volatile("cp.async.cg.shared.global [%0], [%1], 16;" :: "r"(dst), "l"(src))
#define CP_COMMIT() asm volatile("cp.async.commit_group;")
#define CP_WAIT(n)  asm volatile("cp.async.wait_group %0;" :: "n"(n))
#define LDSM4(r, a)                                                           \
    asm volatile("ldmatrix.sync.aligned.m8n8.x4.shared.b16 {%0,%1,%2,%3}, [%4];" \
        : "=r"((r)[0]), "=r"((r)[1]), "=r"((r)[2]), "=r"((r)[3]) : "r"(a))
#define MMA16816(d, a, b)                                                     \
    asm volatile("mma.sync.aligned.m16n8k16.row.col.f32.f16.f16.f32 "        \
        "{%0,%1,%2,%3}, {%4,%5,%6,%7}, {%8,%9}, {%0,%1,%2,%3};"              \
        : "+f"((d)[0]), "+f"((d)[1]), "+f"((d)[2]), "+f"((d)[3])             \
        : "r"((a)[0]), "r"((a)[1]), "r"((a)[2]), "r"((a)[3]),                \
          "r"((b)[0]), "r"((b)[1]))

__device__ __forceinline__ float bmax(float v, int m) {
    return fmaxf(v, __shfl_xor_sync(0xffffffffu, v, m));
}
__device__ __forceinline__ float bmin(float v, int m) {
    return fminf(v, __shfl_xor_sync(0xffffffffu, v, m));
}

// ------------------------------------------------------------------
// normalize: warp per row; per-block int64-vs-int32 detection;
// also resets per-row AP/AN and (block 0) scalar state.
//
// Detection: the 8 odd words t32[2*(row&4095)+1] (all indices <8192,
// in-bounds for either dtype). int64 buffer (values<512) -> all zero;
// int32 buffer -> random targets, all-zero prob (1/512)^8 ~ 2e-22.
// ------------------------------------------------------------------
__global__ __launch_bounds__(256) void norm_kernel(const float* __restrict__ in,
                                                   const int* __restrict__ t32) {
    int row = blockIdx.x * 8 + (threadIdx.x >> 5);
    int lane = threadIdx.x & 31;

    int odd = 0;
    if (lane == 0) odd = t32[2 * (row & 4095) + 1];
    int any = __syncthreads_or(odd);
    bool is64 = (any == 0);

    const float4* p = (const float4*)(in + (size_t)row * DIM);
    float4 a = p[lane * 2];
    float4 b = p[lane * 2 + 1];
    float v[8] = { a.x, a.y, a.z, a.w, b.x, b.y, b.z, b.w };

    float s = 0.0f;
    #pragma unroll
    for (int k = 0; k < 8; k++) s = fmaf(v[k], v[k], s);
    #pragma unroll
    for (int m = 16; m > 0; m >>= 1) s += __shfl_xor_sync(0xffffffffu, s, m);

    float inv = 1.0f / (sqrtf(s) + 1e-12f);
    float x[8];
    float s2 = 0.0f;
    #pragma unroll
    for (int k = 0; k < 8; k++) { x[k] = v[k] * inv; s2 = fmaf(x[k], x[k], s2); }
    #pragma unroll
    for (int m = 16; m > 0; m >>= 1) s2 += __shfl_xor_sync(0xffffffffu, s2, m);

    __half hi[8];
    #pragma unroll
    for (int k = 0; k < 8; k++) hi[k] = __float2half_rn(x[k]);
    *(uint4*)(g_Xhi + (size_t)row * DIM + lane * 8) = *(const uint4*)hi;

    if (lane == 0) {
        g_SQ[row] = s2;
        g_TGT[row] = is64 ? t32[2 * row] : t32[row];
        g_AP[row] = 0u;
        g_AN[row] = 0x7f800000u;
    }
    if (blockIdx.x == 0 && threadIdx.x == 0) {
        g_SUM = 0ull;
        g_DONE = 0u;
    }
}

// ------------------------------------------------------------------
__device__ __forceinline__ void load_stage(
    uint32_t sb, int stg, int k0, int tid,
    const __half* a0, const __half* b0)
{
    uint32_t base = sb + S_STAGE(stg);
    const __half* src[2] = { a0 + k0, b0 + k0 };
    #pragma unroll
    for (int p = 0; p < 2; p++) {
        uint32_t tb = base + p * 16384;
        #pragma unroll
        for (int i = 0; i < 4; i++) {
            int v = tid + i * 256;
            int r = v >> 3, c8 = v & 7;
            uint32_t d = tb + r * 128 + ((c8 ^ (r & 7)) << 4);
            CP16(d, src[p] + (size_t)r * DIM + c8 * 8);
        }
    }
    CP_COMMIT();
}

// 256 threads: 8 warps in a 2x4 grid, each warp owns a 64x32 subtile
// (identical mainloop to the measured-best config)
__global__ __launch_bounds__(256, 2) void pair_kernel() {
    extern __shared__ char dsm[];
    uint32_t raw = smem_u32(dsm);
    uint32_t sb = (raw + 1023u) & ~1023u;
    char* ab = dsm + (sb - raw);

    // triangular tile index -> (it, jt), it <= jt
    int t = blockIdx.x;
    int it = (int)((129.0 - sqrt(16641.0 - 8.0 * (double)t)) * 0.5);
    while ((it + 1) * (129 - (it + 1)) / 2 <= t) it++;
    while (it * (129 - it) / 2 > t) it--;
    int jt = it + (t - it * (129 - it) / 2);

    const int rowBase = it * 128;
    const int colBase = jt * 128;
    const bool diag = (it == jt);

    const int tid = threadIdx.x;
    const int wid = tid >> 5;
    const int lane = tid & 31;
    const int wm = wid & 1;
    const int wn = wid >> 1;

    if (tid < 128) {
        ((int*)(ab + S_LABR))[tid]  = g_TGT[rowBase + tid];
        ((float*)(ab + S_SQR))[tid] = g_SQ[rowBase + tid];
    } else {
        int u = tid - 128;
        ((int*)(ab + S_LABC))[u]  = g_TGT[colBase + u];
        ((float*)(ab + S_SQC))[u] = g_SQ[colBase + u];
    }

    const __half* a0 = g_Xhi + (size_t)rowBase * DIM;
    const __half* b0 = g_Xhi + (size_t)colBase * DIM;

    float acc[4][4][4];
    #pragma unroll
    for (int mf = 0; mf < 4; mf++)
        #pragma unroll
        for (int nf = 0; nf < 4; nf++)
            #pragma unroll
            for (int e = 0; e < 4; e++) acc[mf][nf][e] = 0.0f;

    int arow[4], brow[4];
    #pragma unroll
    for (int mf = 0; mf < 4; mf++) arow[mf] = wm * 64 + mf * 16 + (lane & 15);
    #pragma unroll
    for (int nf = 0; nf < 4; nf++) brow[nf] = wn * 32 + nf * 8 + (lane & 7);
    const int ahalf = lane >> 4;
    const int bq = lane >> 3;

    load_stage(sb, 0, 0, tid, a0, b0);

    #pragma unroll 1
    for (int c = 0; c < 4; c++) {
        if (c < 3) {
            load_stage(sb, (c + 1) & 1, (c + 1) * 64, tid, a0, b0);
            CP_WAIT(1);
        } else {
            CP_WAIT(0);
        }
        __syncthreads();

        uint32_t base = sb + S_STAGE(c & 1);
        #pragma unroll
        for (int s2 = 0; s2 < 2; s2++) {
            uint32_t bh[4][4];
            #pragma unroll
            for (int nf = 0; nf < 4; nf++) {
                uint32_t swo = (((s2 * 4 + bq) ^ (brow[nf] & 7)) << 4);
                LDSM4(bh[nf], base + T_BHI + brow[nf] * 128 + swo);
            }
            #pragma unroll
            for (int ks = 0; ks < 2; ks++) {
                int s = s2 * 2 + ks;
                uint32_t ah[4][4];
                #pragma unroll
                for (int mf = 0; mf < 4; mf++) {
                    uint32_t swo = (((s * 2 + ahalf) ^ (arow[mf] & 7)) << 4);
                    LDSM4(ah[mf], base + T_AHI + arow[mf] * 128 + swo);
                }
                #pragma unroll
                for (int mf = 0; mf < 4; mf++)
                    #pragma unroll
                    for (int nf = 0; nf < 4; nf++)
                        MMA16816(acc[mf][nf], ah[mf], &bh[nf][2 * ks]);
            }
        }
        __syncthreads();
    }

    // ---- epilogue: dual-direction masked reduction ----
    int rlab[4][2], clab[4][2];
    float rsqv[4][2], csqv[4][2];
    #pragma unroll
    for (int mf = 0; mf < 4; mf++)
        #pragma unroll
        for (int sl = 0; sl < 2; sl++) {
            int r = wm * 64 + mf * 16 + sl * 8 + (lane >> 2);
            rlab[mf][sl] = ((const int*)(ab + S_LABR))[r];
            rsqv[mf][sl] = ((const float*)(ab + S_SQR))[r];
        }
    #pragma unroll
    for (int nf = 0; nf < 4; nf++)
        #pragma unroll
        for (int cp = 0; cp < 2; cp++) {
            int cc = wn * 32 + nf * 8 + (lane & 3) * 2 + cp;
            clab[nf][cp] = ((const int*)(ab + S_LABC))[cc];
            csqv[nf][cp] = ((const float*)(ab + S_SQC))[cc];
        }

    float apR[4][2], anR[4][2], apC[4][2], anC[4][2];
    #pragma unroll
    for (int q = 0; q < 4; q++)
        #pragma unroll
        for (int h = 0; h < 2; h++) {
            apR[q][h] = 0.0f; anR[q][h] = INFINITY;
            apC[q][h] = 0.0f; anC[q][h] = INFINITY;
        }

    #pragma unroll
    for (int mf = 0; mf < 4; mf++)
        #pragma unroll
        for (int nf = 0; nf < 4; nf++)
            #pragma unroll
            for (int e = 0; e < 4; e++) {
                int sl = e >> 1, cp = e & 1;
                int rl = wm * 64 + mf * 16 + sl * 8 + (lane >> 2);
                int cl = wn * 32 + nf * 8 + (lane & 3) * 2 + cp;
                float arg = fmaxf(
                    fmaf(-2.0f, acc[mf][nf][e], rsqv[mf][sl] + csqv[nf][cp]),
                    1e-12f);
                bool skip = diag && (rl == cl);
                if (!skip) {
                    if (rlab[mf][sl] == clab[nf][cp]) {
                        apR[mf][sl] = fmaxf(apR[mf][sl], arg);
                        apC[nf][cp] = fmaxf(apC[nf][cp], arg);
                    } else {
                        anR[mf][sl] = fminf(anR[mf][sl], arg);
                        anC[nf][cp] = fminf(anC[nf][cp], arg);
                    }
                }
            }

    float* rrap = (float*)(ab + S_RRAP);
    float* rran = (float*)(ab + S_RRAN);
    float* ccap = (float*)(ab + S_CCAP);
    float* ccan = (float*)(ab + S_CCAN);

    #pragma unroll
    for (int mf = 0; mf < 4; mf++)
        #pragma unroll
        for (int sl = 0; sl < 2; sl++) {
            float ap = bmax(bmax(apR[mf][sl], 1), 2);
            float an = bmin(bmin(anR[mf][sl], 1), 2);
            int r = wm * 64 + mf * 16 + sl * 8 + (lane >> 2);
            if ((lane & 3) == 0) {
                rrap[r * 4 + wn] = ap;
                rran[r * 4 + wn] = an;
            }
        }
    #pragma unroll
    for (int nf = 0; nf < 4; nf++)
        #pragma unroll
        for (int cp = 0; cp < 2; cp++) {
            float ap = bmax(bmax(bmax(apC[nf][cp], 4), 8), 16);
            float an = bmin(bmin(bmin(anC[nf][cp], 4), 8), 16);
            int cc = wn * 32 + nf * 8 + (lane & 3) * 2 + cp;
            if ((lane >> 2) == 0) {
                ccap[cc * 2 + wm] = ap;
                ccan[cc * 2 + wm] = an;
            }
        }
    __syncthreads();

    if (tid < 128) {
        float ap = fmaxf(fmaxf(rrap[tid * 4 + 0], rrap[tid * 4 + 1]),
                         fmaxf(rrap[tid * 4 + 2], rrap[tid * 4 + 3]));
        float an = fminf(fminf(rran[tid * 4 + 0], rran[tid * 4 + 1]),
                         fminf(rran[tid * 4 + 2], rran[tid * 4 + 3]));
        atomicMax((int*)&g_AP[rowBase + tid], __float_as_int(ap));
        atomicMin((int*)&g_AN[rowBase + tid], __float_as_int(an));

        float apc = fmaxf(ccap[tid * 2 + 0], ccap[tid * 2 + 1]);
        float anc = fminf(ccan[tid * 2 + 0], ccan[tid * 2 + 1]);
        atomicMax((int*)&g_AP[colBase + tid], __float_as_int(apc));
        atomicMin((int*)&g_AN[colBase + tid], __float_as_int(anc));
    }
}

// ------------------------------------------------------------------
// finalize: fixed-point deterministic sum; last block writes
// ------------------------------------------------------------------
__global__ void final_kernel(float* __restrict__ out) {
    int i = blockIdx.x * 256 + threadIdx.x;
    unsigned apb = g_AP[i];
    unsigned anb = g_AN[i];
    float dap = (apb == 0u) ? 0.0f : sqrtf(__uint_as_float(apb));
    float dan = (anb == 0x7f800000u) ? (MARGIN + 1.0f)
                                     : sqrtf(__uint_as_float(anb));
    float term = fmaxf(0.0f, dap - dan + MARGIN);
    unsigned long long fx =
        (unsigned long long)((double)term * 4294967296.0);
    #pragma unroll
    for (int m = 16; m > 0; m >>= 1)
        fx += __shfl_xor_sync(0xffffffffu, fx, m);
    if ((threadIdx.x & 31) == 0) atomicAdd(&g_SUM, fx);

    __syncthreads();
    if (threadIdx.x == 0) {
        __threadfence();
        unsigned old = atomicAdd(&g_DONE, 1u);
        if (old == gridDim.x - 1) {
            unsigned long long s = atomicAdd(&g_SUM, 0ull);
            out[0] = (float)((double)s * (1.0 / 4294967296.0) / (double)N);
        }
    }
}

// ------------------------------------------------------------------
extern "C" void kernel_launch(void* const* d_in, const int* in_sizes, int n_in,
                              void* d_out, int out_size) {
    const float* inputs = (const float*)d_in[0];
    const int* targets32 = (const int*)d_in[1];
    float* out = (float*)d_out;

    cudaFuncSetAttribute(pair_kernel,
                         cudaFuncAttributeMaxDynamicSharedMemorySize, SMEM_SZ);

    norm_kernel<<<N / 8, 256>>>(inputs, targets32);
    pair_kernel<<<NTILES, 256, SMEM_SZ>>>();
    final_kernel<<<N / 256, 256>>>(out);
}

// round 17
// speedup vs baseline: 1.0623x; 1.0262x over previous
#include <cuda_runtime.h>
#include <cuda_fp16.h>
#include <math.h>
#include <stdint.h>

#define N 8192
#define DIM 256
#define NT 64
#define NTILES (NT * (NT + 1) / 2)
#define MARGIN 0.3f

// ---- device scratch ----
__device__ __half   g_Xhi[N * DIM];
__device__ float    g_SQ[N];
__device__ int      g_TGT[N];
__device__ unsigned g_AP[N];
__device__ unsigned g_AN[N];
__device__ unsigned long long g_SUM;
__device__ unsigned g_DONE;

// ---- smem layout (relative to 1024-aligned base) ----
// two stages of 2 tiles (Ahi, Bhi), each tile 128 rows x 64 k fp16 = 16KB
#define T_AHI 0
#define T_BHI 16384
#define S_STAGE(s) ((s) * 32768)
#define S_LABR 65536
#define S_LABC (S_LABR + 512)
#define S_SQR  (S_LABC + 512)
#define S_SQC  (S_SQR + 512)
#define S_RRAP (S_SQC + 512)      // 128*2 floats
#define S_RRAN (S_RRAP + 1024)
#define S_CCAP (S_RRAN + 1024)    // 128*2 floats
#define S_CCAN (S_CCAP + 1024)
#define SMEM_SZ (S_CCAN + 1024 + 1024)

// ---- PTX helpers (base sm_103-safe) ----
__device__ __forceinline__ uint32_t smem_u32(const void* p) {
    uint32_t a;
    asm("{ .reg .u64 t; cvta.to.shared.u64 t, %1; cvt.u32.u64 %0, t; }"
        : "=r"(a) : "l"(p));
    return a;
}
#define CP16(dst, src) \
    asm volatile("cp.async.cg.shared.global [%0], [%1], 16;" :: "r"(dst), "l"(src))
#define CP_COMMIT() asm volatile("cp.async.commit_group;")
#define CP_WAIT(n)  asm volatile("cp.async.wait_group %0;" :: "n"(n))
#define LDSM4(r, a)                                                           \
    asm volatile("ldmatrix.sync.aligned.m8n8.x4.shared.b16 {%0,%1,%2,%3}, [%4];" \
        : "=r"((r)[0]), "=r"((r)[1]), "=r"((r)[2]), "=r"((r)[3]) : "r"(a))
#define MMA16816(d, a, b)                                                     \
    asm volatile("mma.sync.aligned.m16n8k16.row.col.f32.f16.f16.f32 "        \
        "{%0,%1,%2,%3}, {%4,%5,%6,%7}, {%8,%9}, {%0,%1,%2,%3};"              \
        : "+f"((d)[0]), "+f"((d)[1]), "+f"((d)[2]), "+f"((d)[3])             \
        : "r"((a)[0]), "r"((a)[1]), "r"((a)[2]), "r"((a)[3]),                \
          "r"((b)[0]), "r"((b)[1]))

__device__ __forceinline__ float bmax(float v, int m) {
    return fmaxf(v, __shfl_xor_sync(0xffffffffu, v, m));
}
__device__ __forceinline__ float bmin(float v, int m) {
    return fminf(v, __shfl_xor_sync(0xffffffffu, v, m));
}

// ------------------------------------------------------------------
// normalize: warp per row; per-block dtype detection; init fused
// ------------------------------------------------------------------
__global__ __launch_bounds__(256) void norm_kernel(const float* __restrict__ in,
                                                   const int* __restrict__ t32) {
    int row = blockIdx.x * 8 + (threadIdx.x >> 5);
    int lane = threadIdx.x & 31;

    int odd = 0;
    if (lane == 0) odd = t32[2 * (row & 4095) + 1];
    int any = __syncthreads_or(odd);
    bool is64 = (any == 0);

    const float4* p = (const float4*)(in + (size_t)row * DIM);
    float4 a = p[lane * 2];
    float4 b = p[lane * 2 + 1];
    float v[8] = { a.x, a.y, a.z, a.w, b.x, b.y, b.z, b.w };

    float s = 0.0f;
    #pragma unroll
    for (int k = 0; k < 8; k++) s = fmaf(v[k], v[k], s);
    #pragma unroll
    for (int m = 16; m > 0; m >>= 1) s += __shfl_xor_sync(0xffffffffu, s, m);

    float inv = 1.0f / (sqrtf(s) + 1e-12f);
    float x[8];
    float s2 = 0.0f;
    #pragma unroll
    for (int k = 0; k < 8; k++) { x[k] = v[k] * inv; s2 = fmaf(x[k], x[k], s2); }
    #pragma unroll
    for (int m = 16; m > 0; m >>= 1) s2 += __shfl_xor_sync(0xffffffffu, s2, m);

    __half hi[8];
    #pragma unroll
    for (int k = 0; k < 8; k++) hi[k] = __float2half_rn(x[k]);
    *(uint4*)(g_Xhi + (size_t)row * DIM + lane * 8) = *(const uint4*)hi;

    if (lane == 0) {
        g_SQ[row] = s2;
        g_TGT[row] = is64 ? t32[2 * row] : t32[row];
        g_AP[row] = 0u;
        g_AN[row] = 0x7f800000u;
    }
    if (blockIdx.x == 0 && threadIdx.x == 0) {
        g_SUM = 0ull;
        g_DONE = 0u;
    }
}

// ------------------------------------------------------------------
// stage loader for 128 threads (16 CP16/thread)
// ------------------------------------------------------------------
__device__ __forceinline__ void load_stage(
    uint32_t sb, int stg, int k0, int tid,
    const __half* a0, const __half* b0)
{
    uint32_t base = sb + S_STAGE(stg);
    const __half* src[2] = { a0 + k0, b0 + k0 };
    #pragma unroll
    for (int p = 0; p < 2; p++) {
        uint32_t tb = base + p * 16384;
        #pragma unroll
        for (int i = 0; i < 8; i++) {
            int v = tid + i * 128;
            int r = v >> 3, c8 = v & 7;
            uint32_t d = tb + r * 128 + ((c8 ^ (r & 7)) << 4);
            CP16(d, src[p] + (size_t)r * DIM + c8 * 8);
        }
    }
    CP_COMMIT();
}

// 128 threads: 4 warps in a 2x2 grid, each warp owns a 64x64 subtile
// of the 128x128 CTA tile. Halves smem bytes per MMA vs 64x32 tiles.
__global__ __launch_bounds__(128, 2) void pair_kernel() {
    extern __shared__ char dsm[];
    uint32_t raw = smem_u32(dsm);
    uint32_t sb = (raw + 1023u) & ~1023u;
    char* ab = dsm + (sb - raw);

    // triangular tile index -> (it, jt), it <= jt
    int t = blockIdx.x;
    int it = (int)((129.0 - sqrt(16641.0 - 8.0 * (double)t)) * 0.5);
    while ((it + 1) * (129 - (it + 1)) / 2 <= t) it++;
    while (it * (129 - it) / 2 > t) it--;
    int jt = it + (t - it * (129 - it) / 2);

    const int rowBase = it * 128;
    const int colBase = jt * 128;
    const bool diag = (it == jt);

    const int tid = threadIdx.x;
    const int wid = tid >> 5;
    const int lane = tid & 31;
    const int wm = wid & 1;        // 2 row-warps (64 rows each)
    const int wn = wid >> 1;       // 2 col-warps (64 cols each)

    // meta (all 128 threads load row+col entries)
    ((int*)(ab + S_LABR))[tid]  = g_TGT[rowBase + tid];
    ((float*)(ab + S_SQR))[tid] = g_SQ[rowBase + tid];
    ((int*)(ab + S_LABC))[tid]  = g_TGT[colBase + tid];
    ((float*)(ab + S_SQC))[tid] = g_SQ[colBase + tid];

    const __half* a0 = g_Xhi + (size_t)rowBase * DIM;
    const __half* b0 = g_Xhi + (size_t)colBase * DIM;

    float acc[4][8][4];
    #pragma unroll
    for (int mf = 0; mf < 4; mf++)
        #pragma unroll
        for (int nf = 0; nf < 8; nf++)
            #pragma unroll
            for (int e = 0; e < 4; e++) acc[mf][nf][e] = 0.0f;

    int arow[4], brow[8];
    #pragma unroll
    for (int mf = 0; mf < 4; mf++) arow[mf] = wm * 64 + mf * 16 + (lane & 15);
    #pragma unroll
    for (int nf = 0; nf < 8; nf++) brow[nf] = wn * 64 + nf * 8 + (lane & 7);
    const int ahalf = lane >> 4;
    const int bq = lane >> 3;

    load_stage(sb, 0, 0, tid, a0, b0);

    #pragma unroll 1
    for (int c = 0; c < 4; c++) {
        if (c < 3) {
            load_stage(sb, (c + 1) & 1, (c + 1) * 64, tid, a0, b0);
            CP_WAIT(1);
        } else {
            CP_WAIT(0);
        }
        __syncthreads();

        uint32_t base = sb + S_STAGE(c & 1);
        #pragma unroll
        for (int s2 = 0; s2 < 2; s2++) {
            uint32_t bh[8][4];
            #pragma unroll
            for (int nf = 0; nf < 8; nf++) {
                uint32_t swo = (((s2 * 4 + bq) ^ (brow[nf] & 7)) << 4);
                LDSM4(bh[nf], base + T_BHI + brow[nf] * 128 + swo);
            }
            #pragma unroll
            for (int ks = 0; ks < 2; ks++) {
                int s = s2 * 2 + ks;
                uint32_t ah[4][4];
                #pragma unroll
                for (int mf = 0; mf < 4; mf++) {
                    uint32_t swo = (((s * 2 + ahalf) ^ (arow[mf] & 7)) << 4);
                    LDSM4(ah[mf], base + T_AHI + arow[mf] * 128 + swo);
                }
                #pragma unroll
                for (int mf = 0; mf < 4; mf++)
                    #pragma unroll
                    for (int nf = 0; nf < 8; nf++)
                        MMA16816(acc[mf][nf], ah[mf], &bh[nf][2 * ks]);
            }
        }
        __syncthreads();
    }

    // ---- epilogue: dual-direction masked reduction ----
    int rlab[4][2], clab[8][2];
    float rsqv[4][2], csqv[8][2];
    #pragma unroll
    for (int mf = 0; mf < 4; mf++)
        #pragma unroll
        for (int sl = 0; sl < 2; sl++) {
            int r = wm * 64 + mf * 16 + sl * 8 + (lane >> 2);
            rlab[mf][sl] = ((const int*)(ab + S_LABR))[r];
            rsqv[mf][sl] = ((const float*)(ab + S_SQR))[r];
        }
    #pragma unroll
    for (int nf = 0; nf < 8; nf++)
        #pragma unroll
        for (int cp = 0; cp < 2; cp++) {
            int cc = wn * 64 + nf * 8 + (lane & 3) * 2 + cp;
            clab[nf][cp] = ((const int*)(ab + S_LABC))[cc];
            csqv[nf][cp] = ((const float*)(ab + S_SQC))[cc];
        }

    float apR[4][2], anR[4][2], apC[8][2], anC[8][2];
    #pragma unroll
    for (int q = 0; q < 4; q++)
        #pragma unroll
        for (int h = 0; h < 2; h++) { apR[q][h] = 0.0f; anR[q][h] = INFINITY; }
    #pragma unroll
    for (int q = 0; q < 8; q++)
        #pragma unroll
        for (int h = 0; h < 2; h++) { apC[q][h] = 0.0f; anC[q][h] = INFINITY; }

    #pragma unroll
    for (int mf = 0; mf < 4; mf++)
        #pragma unroll
        for (int nf = 0; nf < 8; nf++)
            #pragma unroll
            for (int e = 0; e < 4; e++) {
                int sl = e >> 1, cp = e & 1;
                int rl = wm * 64 + mf * 16 + sl * 8 + (lane >> 2);
                int cl = wn * 64 + nf * 8 + (lane & 3) * 2 + cp;
                float arg = fmaxf(
                    fmaf(-2.0f, acc[mf][nf][e], rsqv[mf][sl] + csqv[nf][cp]),
                    1e-12f);
                bool skip = diag && (rl == cl);
                if (!skip) {
                    if (rlab[mf][sl] == clab[nf][cp]) {
                        apR[mf][sl] = fmaxf(apR[mf][sl], arg);
                        apC[nf][cp] = fmaxf(apC[nf][cp], arg);
                    } else {
                        anR[mf][sl] = fminf(anR[mf][sl], arg);
                        anC[nf][cp] = fminf(anC[nf][cp], arg);
                    }
                }
            }

    float* rrap = (float*)(ab + S_RRAP);
    float* rran = (float*)(ab + S_RRAN);
    float* ccap = (float*)(ab + S_CCAP);
    float* ccan = (float*)(ab + S_CCAN);

    // row direction: reduce over lane&3
    #pragma unroll
    for (int mf = 0; mf < 4; mf++)
        #pragma unroll
        for (int sl = 0; sl < 2; sl++) {
            float ap = bmax(bmax(apR[mf][sl], 1), 2);
            float an = bmin(bmin(anR[mf][sl], 1), 2);
            int r = wm * 64 + mf * 16 + sl * 8 + (lane >> 2);
            if ((lane & 3) == 0) {
                rrap[r * 2 + wn] = ap;
                rran[r * 2 + wn] = an;
            }
        }
    // col direction: reduce over lane>>2
    #pragma unroll
    for (int nf = 0; nf < 8; nf++)
        #pragma unroll
        for (int cp = 0; cp < 2; cp++) {
            float ap = bmax(bmax(bmax(apC[nf][cp], 4), 8), 16);
            float an = bmin(bmin(bmin(anC[nf][cp], 4), 8), 16);
            int cc = wn * 64 + nf * 8 + (lane & 3) * 2 + cp;
            if ((lane >> 2) == 0) {
                ccap[cc * 2 + wm] = ap;
                ccan[cc * 2 + wm] = an;
            }
        }
    __syncthreads();

    {
        float ap = fmaxf(rrap[tid * 2 + 0], rrap[tid * 2 + 1]);
        float an = fminf(rran[tid * 2 + 0], rran[tid * 2 + 1]);
        atomicMax((int*)&g_AP[rowBase + tid], __float_as_int(ap));
        atomicMin((int*)&g_AN[rowBase + tid], __float_as_int(an));

        float apc = fmaxf(ccap[tid * 2 + 0], ccap[tid * 2 + 1]);
        float anc = fminf(ccan[tid * 2 + 0], ccan[tid * 2 + 1]);
        atomicMax((int*)&g_AP[colBase + tid], __float_as_int(apc));
        atomicMin((int*)&g_AN[colBase + tid], __float_as_int(anc));
    }
}

// ------------------------------------------------------------------
// finalize: fixed-point deterministic sum; last block writes
// ------------------------------------------------------------------
__global__ void final_kernel(float* __restrict__ out) {
    int i = blockIdx.x * 256 + threadIdx.x;
    unsigned apb = g_AP[i];
    unsigned anb = g_AN[i];
    float dap = (apb == 0u) ? 0.0f : sqrtf(__uint_as_float(apb));
    float dan = (anb == 0x7f800000u) ? (MARGIN + 1.0f)
                                     : sqrtf(__uint_as_float(anb));
    float term = fmaxf(0.0f, dap - dan + MARGIN);
    unsigned long long fx =
        (unsigned long long)((double)term * 4294967296.0);
    #pragma unroll
    for (int m = 16; m > 0; m >>= 1)
        fx += __shfl_xor_sync(0xffffffffu, fx, m);
    if ((threadIdx.x & 31) == 0) atomicAdd(&g_SUM, fx);

    __syncthreads();
    if (threadIdx.x == 0) {
        __threadfence();
        unsigned old = atomicAdd(&g_DONE, 1u);
        if (old == gridDim.x - 1) {
            unsigned long long s = atomicAdd(&g_SUM, 0ull);
            out[0] = (float)((double)s * (1.0 / 4294967296.0) / (double)N);
        }
    }
}

// ------------------------------------------------------------------
extern "C" void kernel_launch(void* const* d_in, const int* in_sizes, int n_in,
                              void* d_out, int out_size) {
    const float* inputs = (const float*)d_in[0];
    const int* targets32 = (const int*)d_in[1];
    float* out = (float*)d_out;

    cudaFuncSetAttribute(pair_kernel,
                         cudaFuncAttributeMaxDynamicSharedMemorySize, SMEM_SZ);

    norm_kernel<<<N / 8, 256>>>(inputs, targets32);
    pair_kernel<<<NTILES, 128, SMEM_SZ>>>();
    final_kernel<<<N / 256, 256>>>(out);
}